// round 12
// baseline (speedup 1.0000x reference)
#include <cuda_runtime.h>
#include <cuda_bf16.h>
#include <cstdint>

// Problem constants
#define B_DIM 16
#define P_DIM 87
#define K_DIM 4
#define N_DIM 32768
#define D_MODEL 256
#define HIDDEN 128
#define LOGIT_SCALE 0.125f   // ATTN_SCALE / TAU

// Output layout (flattened tuple, fp32)
#define OUT_PROBS 0
#define OUT_LOGITS 1392
#define OUT_COORDS 2784

// Scratch (no allocations allowed -> __device__ globals; zero-initialized,
// re-zeroed by kernel B's last attn block for graph-replay safety)
__device__ float g_q[64 * D_MODEL];              // final projected queries
__device__ float g_acc[B_DIM * K_DIM * 4];       // per (b,k): sumw, sx, sy, sz
__device__ int   g_attn_done = 0;                // attn block completion counter

#define QP_BLOCKS 64        // 16 row-groups x 4 i-chunks
#define HD_BLOCKS 58        // dense head blocks, 24 rows each = 1392 rows
#define HD_ROWS 24
#define ATTN_BLOCKS 2048    // 128 x-tiles * 16 batches

// ---------------------------------------------------------------------------
// cp.async helpers
// ---------------------------------------------------------------------------
__device__ __forceinline__ void cp16(void* dst, const void* src) {
    uint32_t d = (uint32_t)__cvta_generic_to_shared(dst);
    asm volatile("cp.async.cg.shared.global [%0], [%1], 16;" :: "r"(d), "l"(src));
}
__device__ __forceinline__ void cp4(void* dst, const void* src) {
    uint32_t d = (uint32_t)__cvta_generic_to_shared(dst);
    asm volatile("cp.async.ca.shared.global [%0], [%1], 4;" :: "r"(d), "l"(src));
}
__device__ __forceinline__ void cp_commit() {
    asm volatile("cp.async.commit_group;");
}

// ---------------------------------------------------------------------------
// Kernel A: blocks [0,64) = q projection chunks (atomicAdd into g_q);
//           blocks [64,122) = dense human head (24 rows/block, W1 via smem).
// One wave; runs before the attn kernel.
// ---------------------------------------------------------------------------
__global__ void __launch_bounds__(256)
prep_kernel(const float* __restrict__ oq,
            const float* __restrict__ Wq,
            const float* __restrict__ bq,
            const float* __restrict__ hq,
            const float* __restrict__ W1,
            const float* __restrict__ b1,
            const float* __restrict__ W2,
            const float* __restrict__ b2,
            float* __restrict__ out) {
    __shared__ __align__(16) char smraw[34 * 1024];
    const int t = threadIdx.x;
    const int warp = t >> 5;
    const int lane = t & 31;

    if (blockIdx.x < QP_BLOCKS) {
        // ========== q projection chunk: 4 rows x 64-wide i-chunk ==========
        float* xs = reinterpret_cast<float*>(smraw);              // 256 floats
        float4* part4 = reinterpret_cast<float4*>(smraw + 1024);  // 32 KB
        const int rg = blockIdx.x >> 2;      // row group 0..15
        const int c = blockIdx.x & 3;        // i-chunk 0..3

        {
            const int r = t >> 6;
            const int idx = t & 63;
            xs[r * 64 + idx] = oq[(size_t)(rg * 4 + r) * D_MODEL + c * 64 + idx];
        }
        __syncthreads();

        const float4* wqv = reinterpret_cast<const float4*>(Wq);
        float4 aA[4], aB[4];
#pragma unroll
        for (int r = 0; r < 4; r++) { aA[r] = {0,0,0,0}; aB[r] = {0,0,0,0}; }
#pragma unroll
        for (int ii = 0; ii < 8; ii++) {
            const int il = warp * 8 + ii;
            const int ig = c * 64 + il;
            const float4 wa = wqv[ig * 64 + lane];
            const float4 wb = wqv[ig * 64 + 32 + lane];
            const float x0 = xs[il];
            const float x1 = xs[64 + il];
            const float x2 = xs[128 + il];
            const float x3 = xs[192 + il];
            aA[0].x = fmaf(x0, wa.x, aA[0].x); aA[0].y = fmaf(x0, wa.y, aA[0].y);
            aA[0].z = fmaf(x0, wa.z, aA[0].z); aA[0].w = fmaf(x0, wa.w, aA[0].w);
            aB[0].x = fmaf(x0, wb.x, aB[0].x); aB[0].y = fmaf(x0, wb.y, aB[0].y);
            aB[0].z = fmaf(x0, wb.z, aB[0].z); aB[0].w = fmaf(x0, wb.w, aB[0].w);
            aA[1].x = fmaf(x1, wa.x, aA[1].x); aA[1].y = fmaf(x1, wa.y, aA[1].y);
            aA[1].z = fmaf(x1, wa.z, aA[1].z); aA[1].w = fmaf(x1, wa.w, aA[1].w);
            aB[1].x = fmaf(x1, wb.x, aB[1].x); aB[1].y = fmaf(x1, wb.y, aB[1].y);
            aB[1].z = fmaf(x1, wb.z, aB[1].z); aB[1].w = fmaf(x1, wb.w, aB[1].w);
            aA[2].x = fmaf(x2, wa.x, aA[2].x); aA[2].y = fmaf(x2, wa.y, aA[2].y);
            aA[2].z = fmaf(x2, wa.z, aA[2].z); aA[2].w = fmaf(x2, wa.w, aA[2].w);
            aB[2].x = fmaf(x2, wb.x, aB[2].x); aB[2].y = fmaf(x2, wb.y, aB[2].y);
            aB[2].z = fmaf(x2, wb.z, aB[2].z); aB[2].w = fmaf(x2, wb.w, aB[2].w);
            aA[3].x = fmaf(x3, wa.x, aA[3].x); aA[3].y = fmaf(x3, wa.y, aA[3].y);
            aA[3].z = fmaf(x3, wa.z, aA[3].z); aA[3].w = fmaf(x3, wa.w, aA[3].w);
            aB[3].x = fmaf(x3, wb.x, aB[3].x); aB[3].y = fmaf(x3, wb.y, aB[3].y);
            aB[3].z = fmaf(x3, wb.z, aB[3].z); aB[3].w = fmaf(x3, wb.w, aB[3].w);
        }
#pragma unroll
        for (int r = 0; r < 4; r++) {
            part4[(warp * 4 + r) * 64 + lane] = aA[r];
            part4[(warp * 4 + r) * 64 + 32 + lane] = aB[r];
        }
        __syncthreads();

        {
            const int r = t >> 6;
            const int cc = t & 63;
            float4 s = part4[r * 64 + cc];
#pragma unroll
            for (int j = 1; j < 8; j++) {
                const float4 p = part4[(j * 4 + r) * 64 + cc];
                s.x += p.x; s.y += p.y; s.z += p.z; s.w += p.w;
            }
            if (c == 0) {
                const float4 bb = reinterpret_cast<const float4*>(bq)[cc];
                s.x += bb.x; s.y += bb.y; s.z += bb.z; s.w += bb.w;
            }
            float* dst = g_q + (size_t)(rg * 4 + r) * D_MODEL + cc * 4;
            atomicAdd(dst + 0, s.x);
            atomicAdd(dst + 1, s.y);
            atomicAdd(dst + 2, s.z);
            atomicAdd(dst + 3, s.w);
        }
        return;
    }

    // ========== dense human head: 24 rows, W1 in 16KB smem chunks ==========
    const int blk = blockIdx.x - QP_BLOCKS;           // 0..57
    float* w1s = reinterpret_cast<float*>(smraw);                 // 16 KB
    float* xs2 = reinterpret_cast<float*>(smraw + 16384);         // 3 KB
    float* partred = reinterpret_cast<float*>(smraw + 16384 + 3072); // 384 B

    const int g = t >> 7;        // row half: 0 -> rows 0-11, 1 -> rows 12-23
    const int h = t & 127;       // hidden unit
    float acc[12];
#pragma unroll
    for (int r = 0; r < 12; r++) acc[r] = 0.0f;

    const float* hq_blk = hq + (size_t)blk * HD_ROWS * D_MODEL;

    for (int c = 0; c < 8; c++) {
        // W1 chunk: rows [c*32, c*32+32) x 128 cols = contiguous 4096 floats
#pragma unroll
        for (int j = 0; j < 16; j++)
            w1s[j * 256 + t] = W1[c * 4096 + j * 256 + t];
        // x chunk: 24 rows x 32 i's
#pragma unroll
        for (int j = 0; j < 3; j++) {
            const int idx = j * 256 + t;   // 0..767
            const int r = idx >> 5;
            const int i = idx & 31;
            xs2[idx] = hq_blk[(size_t)r * D_MODEL + c * 32 + i];
        }
        __syncthreads();

        const float4* x4 = reinterpret_cast<const float4*>(xs2);
#pragma unroll
        for (int i4 = 0; i4 < 8; i4++) {
            const float w0 = w1s[(i4 * 4 + 0) * 128 + h];
            const float w1v = w1s[(i4 * 4 + 1) * 128 + h];
            const float w2v = w1s[(i4 * 4 + 2) * 128 + h];
            const float w3v = w1s[(i4 * 4 + 3) * 128 + h];
#pragma unroll
            for (int r = 0; r < 12; r++) {
                const float4 xv = x4[(g * 12 + r) * 8 + i4];
                acc[r] = fmaf(xv.x, w0, acc[r]);
                acc[r] = fmaf(xv.y, w1v, acc[r]);
                acc[r] = fmaf(xv.z, w2v, acc[r]);
                acc[r] = fmaf(xv.w, w3v, acc[r]);
            }
        }
        __syncthreads();
    }

    // epilogue: relu, *W2, reduce over 128 h's (4 warps per row-half)
    const float bb = b1[h];
    const float w2h = W2[h];
#pragma unroll
    for (int r = 0; r < 12; r++) {
        float v = fmaxf(acc[r] + bb, 0.0f) * w2h;
#pragma unroll
        for (int off = 16; off > 0; off >>= 1)
            v += __shfl_xor_sync(0xffffffffu, v, off);
        if (lane == 0)
            partred[(g * 12 + r) * 4 + (warp & 3)] = v;
    }
    __syncthreads();
    if (t < HD_ROWS) {
        const float logit = partred[t * 4 + 0] + partred[t * 4 + 1] +
                            partred[t * 4 + 2] + partred[t * 4 + 3] + b2[0];
        const int row = blk * HD_ROWS + t;
        out[OUT_LOGITS + row] = logit;
        out[OUT_PROBS + row] = 1.0f / (1.0f + __expf(-logit));
    }
}

// ---------------------------------------------------------------------------
// Kernel B: pure attention pooling (2048 blocks). Last block finalizes
// coords and resets scratch for the next graph replay.
// ---------------------------------------------------------------------------
#define TR 32
#define NT 8
#define ATTN_SMEM_BYTES (2*TR*256*4 + 2*TR*3*4 + 32*16)  // 66816

__global__ void __launch_bounds__(256, 3)
attn_kernel(const float* __restrict__ feats,
            const float* __restrict__ xyz,
            float* __restrict__ out) {
    extern __shared__ float sm[];
    const int t = threadIdx.x;
    const int warp = t >> 5;
    const int lane = t & 31;

    const int abx = blockIdx.x;               // 0..2047
    const int b = abx >> 7;                   // batch 0..15
    const int xt = abx & 127;                 // x-tile 0..127
    const int row0 = xt * (TR * NT);

    float* buf = sm;                              // 2 * 8192 floats
    float* xyzs = sm + 2 * TR * 256;              // 2 * 96 floats
    float4* red4 = reinterpret_cast<float4*>(sm + 2 * TR * 256 + 2 * TR * 3);
    __shared__ int is_last;

    const float* fbase = feats + ((size_t)b * N_DIM + row0) * D_MODEL;
    const float* xbase = xyz + ((size_t)b * N_DIM + row0) * 3;

    // prologue: issue tiles 0 and 1
#pragma unroll
    for (int pt = 0; pt < 2; pt++) {
        const float* src = fbase + pt * TR * 256;
        float* dst = buf + pt * TR * 256;
#pragma unroll
        for (int j = 0; j < 8; j++) {
            const int f = (t + j * 256) * 4;
            cp16(dst + f, src + f);
        }
        if (t < TR * 3) cp4(xyzs + pt * TR * 3 + t, xbase + pt * TR * 3 + t);
        cp_commit();
    }

    // q in registers — final at kernel entry (kernel-boundary ordering)
    const float4* q4 =
        reinterpret_cast<const float4*>(g_q + (size_t)b * K_DIM * D_MODEL);
    float4 qa[K_DIM], qb[K_DIM];
#pragma unroll
    for (int k = 0; k < K_DIM; k++) {
        qa[k] = q4[k * 64 + lane];
        qb[k] = q4[k * 64 + 32 + lane];
    }

    float aw = 0.0f, ax = 0.0f, ay = 0.0f, az = 0.0f;
    const int myrow = (lane >> 2) & 3;

#pragma unroll 1
    for (int tile = 0; tile < NT; tile++) {
        if (tile < NT - 1) asm volatile("cp.async.wait_group 1;");
        else               asm volatile("cp.async.wait_group 0;");
        __syncthreads();

        const int bi = tile & 1;
        const float4* B4 = reinterpret_cast<const float4*>(buf + bi * TR * 256);
        const float* XZ = xyzs + bi * TR * 3;

        float keep = 0.0f;
#pragma unroll
        for (int rb = 0; rb < 4; rb++) {
            const int row = warp * 4 + rb;
            const float4 fa = B4[row * 64 + lane];
            const float4 fb = B4[row * 64 + 32 + lane];

            float p0, p1, p2, p3;
            p0 = fa.x * qa[0].x; p0 = fmaf(fa.y, qa[0].y, p0);
            p0 = fmaf(fa.z, qa[0].z, p0); p0 = fmaf(fa.w, qa[0].w, p0);
            p0 = fmaf(fb.x, qb[0].x, p0); p0 = fmaf(fb.y, qb[0].y, p0);
            p0 = fmaf(fb.z, qb[0].z, p0); p0 = fmaf(fb.w, qb[0].w, p0);

            p1 = fa.x * qa[1].x; p1 = fmaf(fa.y, qa[1].y, p1);
            p1 = fmaf(fa.z, qa[1].z, p1); p1 = fmaf(fa.w, qa[1].w, p1);
            p1 = fmaf(fb.x, qb[1].x, p1); p1 = fmaf(fb.y, qb[1].y, p1);
            p1 = fmaf(fb.z, qb[1].z, p1); p1 = fmaf(fb.w, qb[1].w, p1);

            p2 = fa.x * qa[2].x; p2 = fmaf(fa.y, qa[2].y, p2);
            p2 = fmaf(fa.z, qa[2].z, p2); p2 = fmaf(fa.w, qa[2].w, p2);
            p2 = fmaf(fb.x, qb[2].x, p2); p2 = fmaf(fb.y, qb[2].y, p2);
            p2 = fmaf(fb.z, qb[2].z, p2); p2 = fmaf(fb.w, qb[2].w, p2);

            p3 = fa.x * qa[3].x; p3 = fmaf(fa.y, qa[3].y, p3);
            p3 = fmaf(fa.z, qa[3].z, p3); p3 = fmaf(fa.w, qa[3].w, p3);
            p3 = fmaf(fb.x, qb[3].x, p3); p3 = fmaf(fb.y, qb[3].y, p3);
            p3 = fmaf(fb.w, qb[3].w, fmaf(fb.z, qb[3].z, p3));

            float t1 = (lane & 1) ? p0 : p1;
            t1 = __shfl_xor_sync(0xffffffffu, t1, 1);
            float t2 = (lane & 1) ? p2 : p3;
            t2 = __shfl_xor_sync(0xffffffffu, t2, 1);
            const float aab = ((lane & 1) ? p1 : p0) + t1;
            const float ccd = ((lane & 1) ? p3 : p2) + t2;
            float t3 = (lane & 2) ? aab : ccd;
            t3 = __shfl_xor_sync(0xffffffffu, t3, 2);
            float v = ((lane & 2) ? ccd : aab) + t3;
            v += __shfl_xor_sync(0xffffffffu, v, 4);
            v += __shfl_xor_sync(0xffffffffu, v, 8);
            v += __shfl_xor_sync(0xffffffffu, v, 16);
            if (myrow == rb) keep = v;
        }

        const float wgt = __expf(keep * LOGIT_SCALE);
        if (lane < 16) {
            const int row = warp * 4 + myrow;
            const float px = XZ[row * 3 + 0];
            const float py = XZ[row * 3 + 1];
            const float pz = XZ[row * 3 + 2];
            aw += wgt;
            ax = fmaf(wgt, px, ax);
            ay = fmaf(wgt, py, ay);
            az = fmaf(wgt, pz, az);
        }

        __syncthreads();

        if (tile + 2 < NT) {
            const float* src = fbase + (tile + 2) * TR * 256;
            float* dst = buf + bi * TR * 256;
#pragma unroll
            for (int j = 0; j < 8; j++) {
                const int f = (t + j * 256) * 4;
                cp16(dst + f, src + f);
            }
            if (t < TR * 3)
                cp4(xyzs + bi * TR * 3 + t, xbase + (tile + 2) * TR * 3 + t);
            cp_commit();
        }
    }

#pragma unroll
    for (int off = 4; off < 32; off <<= 1) {
        aw += __shfl_xor_sync(0xffffffffu, aw, off);
        ax += __shfl_xor_sync(0xffffffffu, ax, off);
        ay += __shfl_xor_sync(0xffffffffu, ay, off);
        az += __shfl_xor_sync(0xffffffffu, az, off);
    }
    if (lane < 4)
        red4[warp * 4 + lane] = make_float4(aw, ax, ay, az);
    __syncthreads();

    if (t < 16) {
        const int k = t >> 2;
        const int c = t & 3;
        const float* rf = reinterpret_cast<const float*>(red4);
        float s = 0.0f;
#pragma unroll
        for (int j = 0; j < 8; j++) s += rf[(j * 4 + k) * 4 + c];
        atomicAdd(&g_acc[((size_t)b * K_DIM + k) * 4 + c], s);
    }
    __syncthreads();

    // last attn block finalizes coords and resets state for the next replay
    if (t == 0) {
        __threadfence();
        const int old = atomicAdd(&g_attn_done, 1);
        is_last = (old == ATTN_BLOCKS - 1);
    }
    __syncthreads();
    if (is_last) {
        if (t < B_DIM * K_DIM) {
            volatile float* ga = g_acc + (size_t)t * 4;
            const float sw = ga[0];
            const float sx = ga[1];
            const float sy = ga[2];
            const float sz = ga[3];
            const float inv = 1.0f / sw;
            out[OUT_COORDS + t * 3 + 0] = sx * inv;
            out[OUT_COORDS + t * 3 + 1] = sy * inv;
            out[OUT_COORDS + t * 3 + 2] = sz * inv;
            ga[0] = 0.0f; ga[1] = 0.0f; ga[2] = 0.0f; ga[3] = 0.0f;
        }
        // re-zero g_q (64*256 floats) for the next launch's qproj atomics
#pragma unroll
        for (int j = 0; j < 64; j++)
            g_q[t + j * 256] = 0.0f;
        __syncthreads();
        if (t == 0) {
            g_attn_done = 0;
            __threadfence();
        }
    }
}

// ---------------------------------------------------------------------------
extern "C" void kernel_launch(void* const* d_in, const int* in_sizes, int n_in,
                              void* d_out, int out_size) {
    const float* hq    = (const float*)d_in[0];
    const float* oq    = (const float*)d_in[1];
    const float* feats = (const float*)d_in[2];
    const float* xyz   = (const float*)d_in[3];
    const float* W1    = (const float*)d_in[4];
    const float* b1    = (const float*)d_in[5];
    const float* W2    = (const float*)d_in[6];
    const float* b2    = (const float*)d_in[7];
    const float* Wq    = (const float*)d_in[8];
    const float* bq    = (const float*)d_in[9];
    float* out = (float*)d_out;

    cudaFuncSetAttribute(attn_kernel,
                         cudaFuncAttributeMaxDynamicSharedMemorySize,
                         ATTN_SMEM_BYTES);

    prep_kernel<<<QP_BLOCKS + HD_BLOCKS, 256>>>(
        oq, Wq, bq, hq, W1, b1, W2, b2, out);

    attn_kernel<<<ATTN_BLOCKS, 256, ATTN_SMEM_BYTES>>>(feats, xyz, out);
}

// round 13
// speedup vs baseline: 1.0768x; 1.0768x over previous
#include <cuda_runtime.h>
#include <cuda_bf16.h>
#include <cstdint>

// Problem constants
#define B_DIM 16
#define P_DIM 87
#define K_DIM 4
#define N_DIM 32768
#define D_MODEL 256
#define HIDDEN 128
#define LOGIT_SCALE 0.125f   // ATTN_SCALE / TAU

// Output layout (flattened tuple, fp32)
#define OUT_PROBS 0
#define OUT_LOGITS 1392
#define OUT_COORDS 2784

// Scratch (no allocations allowed -> __device__ globals; zero-initialized,
// re-zeroed by the last attn block each launch for graph-replay safety)
__device__ float g_q[64 * D_MODEL];              // final projected queries
__device__ float g_acc[B_DIM * K_DIM * 4];       // per (b,k): sumw, sx, sy, sz
__device__ int   g_done = 0;                     // qproj completion counter
__device__ int   g_attn_done = 0;                // attn block completion counter

#define QP_BLOCKS 64        // 16 row-groups x 4 i-chunks
#define ATTN_BLOCKS 2048    // 128 x-tiles * 16 batches
#define HH_BLOCKS 348       // human-head blocks, 4 rows each
#define ATTN_BASE QP_BLOCKS                 // 64
#define HH_BASE (QP_BLOCKS + ATTN_BLOCKS)   // 2112

// Attn tiling: 16-row (16 KB) tiles, double-buffered, 16 tiles per block.
#define TR 16
#define NT 16
// smem: 2*16KB tiles + 2*48 xyz floats + 32 float4 red + qproj needs 33792
#define SMEM_BYTES 34048

// ---------------------------------------------------------------------------
// cp.async helpers
// ---------------------------------------------------------------------------
__device__ __forceinline__ void cp16(void* dst, const void* src) {
    uint32_t d = (uint32_t)__cvta_generic_to_shared(dst);
    asm volatile("cp.async.cg.shared.global [%0], [%1], 16;" :: "r"(d), "l"(src));
}
__device__ __forceinline__ void cp4(void* dst, const void* src) {
    uint32_t d = (uint32_t)__cvta_generic_to_shared(dst);
    asm volatile("cp.async.ca.shared.global [%0], [%1], 4;" :: "r"(d), "l"(src));
}
__device__ __forceinline__ void cp_commit() {
    asm volatile("cp.async.commit_group;");
}
__device__ __forceinline__ int ld_acquire(const int* p) {
    int v;
    asm volatile("ld.acquire.gpu.global.b32 %0, [%1];" : "=r"(v) : "l"(p));
    return v;
}

// ---------------------------------------------------------------------------
// Single fused kernel (R9-proven structure, higher-occupancy attn):
//   [0, 64):        q projection chunks -> atomicAdd g_q, release g_done
//   [64, 2112):     attention pooling (prefetch, spin, mainloop)
//   [2112, 2460):   human MLP head
// ---------------------------------------------------------------------------
__global__ void __launch_bounds__(256, 4)
fused_kernel(const float* __restrict__ feats,
             const float* __restrict__ xyz,
             const float* __restrict__ hq,
             const float* __restrict__ oq,
             const float* __restrict__ W1,
             const float* __restrict__ b1,
             const float* __restrict__ W2,
             const float* __restrict__ b2,
             const float* __restrict__ Wq,
             const float* __restrict__ bq,
             float* __restrict__ out) {
    extern __shared__ float sm[];
    const int t = threadIdx.x;
    const int warp = t >> 5;
    const int lane = t & 31;

    if (blockIdx.x < QP_BLOCKS) {
        // ========== q projection chunk: 4 rows x 64-wide i-chunk ==========
        float* xs = sm;                                        // 256 floats
        float4* part4 = reinterpret_cast<float4*>(sm + 256);   // 32 KB
        const int rg = blockIdx.x >> 2;
        const int c = blockIdx.x & 3;

        {
            const int r = t >> 6;
            const int idx = t & 63;
            xs[r * 64 + idx] = oq[(size_t)(rg * 4 + r) * D_MODEL + c * 64 + idx];
        }
        __syncthreads();

        const float4* wqv = reinterpret_cast<const float4*>(Wq);
        float4 aA[4], aB[4];
#pragma unroll
        for (int r = 0; r < 4; r++) { aA[r] = {0,0,0,0}; aB[r] = {0,0,0,0}; }
#pragma unroll
        for (int ii = 0; ii < 8; ii++) {
            const int il = warp * 8 + ii;
            const int ig = c * 64 + il;
            const float4 wa = wqv[ig * 64 + lane];
            const float4 wb = wqv[ig * 64 + 32 + lane];
            const float x0 = xs[il];
            const float x1 = xs[64 + il];
            const float x2 = xs[128 + il];
            const float x3 = xs[192 + il];
            aA[0].x = fmaf(x0, wa.x, aA[0].x); aA[0].y = fmaf(x0, wa.y, aA[0].y);
            aA[0].z = fmaf(x0, wa.z, aA[0].z); aA[0].w = fmaf(x0, wa.w, aA[0].w);
            aB[0].x = fmaf(x0, wb.x, aB[0].x); aB[0].y = fmaf(x0, wb.y, aB[0].y);
            aB[0].z = fmaf(x0, wb.z, aB[0].z); aB[0].w = fmaf(x0, wb.w, aB[0].w);
            aA[1].x = fmaf(x1, wa.x, aA[1].x); aA[1].y = fmaf(x1, wa.y, aA[1].y);
            aA[1].z = fmaf(x1, wa.z, aA[1].z); aA[1].w = fmaf(x1, wa.w, aA[1].w);
            aB[1].x = fmaf(x1, wb.x, aB[1].x); aB[1].y = fmaf(x1, wb.y, aB[1].y);
            aB[1].z = fmaf(x1, wb.z, aB[1].z); aB[1].w = fmaf(x1, wb.w, aB[1].w);
            aA[2].x = fmaf(x2, wa.x, aA[2].x); aA[2].y = fmaf(x2, wa.y, aA[2].y);
            aA[2].z = fmaf(x2, wa.z, aA[2].z); aA[2].w = fmaf(x2, wa.w, aA[2].w);
            aB[2].x = fmaf(x2, wb.x, aB[2].x); aB[2].y = fmaf(x2, wb.y, aB[2].y);
            aB[2].z = fmaf(x2, wb.z, aB[2].z); aB[2].w = fmaf(x2, wb.w, aB[2].w);
            aA[3].x = fmaf(x3, wa.x, aA[3].x); aA[3].y = fmaf(x3, wa.y, aA[3].y);
            aA[3].z = fmaf(x3, wa.z, aA[3].z); aA[3].w = fmaf(x3, wa.w, aA[3].w);
            aB[3].x = fmaf(x3, wb.x, aB[3].x); aB[3].y = fmaf(x3, wb.y, aB[3].y);
            aB[3].z = fmaf(x3, wb.z, aB[3].z); aB[3].w = fmaf(x3, wb.w, aB[3].w);
        }
#pragma unroll
        for (int r = 0; r < 4; r++) {
            part4[(warp * 4 + r) * 64 + lane] = aA[r];
            part4[(warp * 4 + r) * 64 + 32 + lane] = aB[r];
        }
        __syncthreads();

        {
            const int r = t >> 6;
            const int cc = t & 63;
            float4 s = part4[r * 64 + cc];
#pragma unroll
            for (int j = 1; j < 8; j++) {
                const float4 p = part4[(j * 4 + r) * 64 + cc];
                s.x += p.x; s.y += p.y; s.z += p.z; s.w += p.w;
            }
            if (c == 0) {
                const float4 bb = reinterpret_cast<const float4*>(bq)[cc];
                s.x += bb.x; s.y += bb.y; s.z += bb.z; s.w += bb.w;
            }
            float* dst = g_q + (size_t)(rg * 4 + r) * D_MODEL + cc * 4;
            atomicAdd(dst + 0, s.x);
            atomicAdd(dst + 1, s.y);
            atomicAdd(dst + 2, s.z);
            atomicAdd(dst + 3, s.w);
        }
        __syncthreads();
        if (t == 0) {
            __threadfence();
            atomicAdd(&g_done, 1);
        }
        return;
    }

    if (blockIdx.x >= HH_BASE) {
        // ================= human head: 4 rows per block =================
        const int blk = blockIdx.x - HH_BASE;
        float* xs = sm;
        float4* part4 = reinterpret_cast<float4*>(sm + 1024);

        const float* src = hq + (size_t)blk * 4 * D_MODEL;
#pragma unroll
        for (int j = 0; j < 4; j++) xs[t + j * 256] = src[t + j * 256];
        __syncthreads();

        const int i0 = warp * 32;
        const float4* w1v = reinterpret_cast<const float4*>(W1);
        float4 a0 = {0,0,0,0}, a1 = {0,0,0,0}, a2 = {0,0,0,0}, a3 = {0,0,0,0};
#pragma unroll 4
        for (int ii = 0; ii < 32; ii++) {
            const int i = i0 + ii;
            const float4 wv = w1v[i * 32 + lane];
            const float x0 = xs[i];
            const float x1 = xs[256 + i];
            const float x2 = xs[512 + i];
            const float x3 = xs[768 + i];
            a0.x = fmaf(x0, wv.x, a0.x); a0.y = fmaf(x0, wv.y, a0.y);
            a0.z = fmaf(x0, wv.z, a0.z); a0.w = fmaf(x0, wv.w, a0.w);
            a1.x = fmaf(x1, wv.x, a1.x); a1.y = fmaf(x1, wv.y, a1.y);
            a1.z = fmaf(x1, wv.z, a1.z); a1.w = fmaf(x1, wv.w, a1.w);
            a2.x = fmaf(x2, wv.x, a2.x); a2.y = fmaf(x2, wv.y, a2.y);
            a2.z = fmaf(x2, wv.z, a2.z); a2.w = fmaf(x2, wv.w, a2.w);
            a3.x = fmaf(x3, wv.x, a3.x); a3.y = fmaf(x3, wv.y, a3.y);
            a3.z = fmaf(x3, wv.z, a3.z); a3.w = fmaf(x3, wv.w, a3.w);
        }
        part4[(warp * 4 + 0) * 32 + lane] = a0;
        part4[(warp * 4 + 1) * 32 + lane] = a1;
        part4[(warp * 4 + 2) * 32 + lane] = a2;
        part4[(warp * 4 + 3) * 32 + lane] = a3;
        __syncthreads();

        if (t < 128) {
            const int r = t >> 5;
            const int l = t & 31;
            float4 s = part4[r * 32 + l];
#pragma unroll
            for (int j = 1; j < 8; j++) {
                const float4 p = part4[(j * 4 + r) * 32 + l];
                s.x += p.x; s.y += p.y; s.z += p.z; s.w += p.w;
            }
            const float4 bb = reinterpret_cast<const float4*>(b1)[l];
            s.x = fmaxf(s.x + bb.x, 0.0f);
            s.y = fmaxf(s.y + bb.y, 0.0f);
            s.z = fmaxf(s.z + bb.z, 0.0f);
            s.w = fmaxf(s.w + bb.w, 0.0f);
            const float4 w2 = reinterpret_cast<const float4*>(W2)[l];
            float v = s.x * w2.x + s.y * w2.y + s.z * w2.z + s.w * w2.w;
#pragma unroll
            for (int off = 16; off > 0; off >>= 1)
                v += __shfl_xor_sync(0xffffffffu, v, off);
            if (l == 0) {
                const int row = blk * 4 + r;
                const float logit = v + b2[0];
                out[OUT_LOGITS + row] = logit;
                out[OUT_PROBS + row] = 1.0f / (1.0f + __expf(-logit));
            }
        }
        return;
    }

    // ================= attention pooling =================
    const int abx = blockIdx.x - ATTN_BASE;   // 0..2047
    const int b = abx >> 7;                   // batch 0..15
    const int xt = abx & 127;                 // x-tile 0..127
    const int row0 = xt * (TR * NT);          // 256 rows per block

    float* buf = sm;                              // 2 * 4096 floats (32 KB)
    float* xyzs = sm + 2 * TR * 256;              // 2 * 48 floats
    float4* red4 = reinterpret_cast<float4*>(sm + 2 * TR * 256 + 2 * TR * 3);
    __shared__ int is_last;

    const float* fbase = feats + ((size_t)b * N_DIM + row0) * D_MODEL;
    const float* xbase = xyz + ((size_t)b * N_DIM + row0) * 3;

    // prologue FIRST (independent of g_q): issue tiles 0 and 1
#pragma unroll
    for (int pt = 0; pt < 2; pt++) {
        const float* src = fbase + pt * TR * 256;
        float* dst = buf + pt * TR * 256;
#pragma unroll
        for (int j = 0; j < 4; j++) {
            const int f = (t + j * 256) * 4;
            cp16(dst + f, src + f);
        }
        if (t < TR * 3) cp4(xyzs + pt * TR * 3 + t, xbase + pt * TR * 3 + t);
        cp_commit();
    }

    // acquire-spin until qproj is complete (overlaps tile-0 DRAM fetch)
    if (t == 0) {
        while (ld_acquire(&g_done) < QP_BLOCKS)
            __nanosleep(32);
    }
    __syncthreads();

    // q in registers
    const float4* q4 =
        reinterpret_cast<const float4*>(g_q + (size_t)b * K_DIM * D_MODEL);
    float4 qa[K_DIM], qb[K_DIM];
#pragma unroll
    for (int k = 0; k < K_DIM; k++) {
        qa[k] = q4[k * 64 + lane];
        qb[k] = q4[k * 64 + 32 + lane];
    }

    float aw = 0.0f, ax = 0.0f, ay = 0.0f, az = 0.0f;
    const int myrow = (lane >> 2) & 1;   // 2 rows/warp/tile; lanes<8 accumulate

#pragma unroll 1
    for (int tile = 0; tile < NT; tile++) {
        if (tile < NT - 1) asm volatile("cp.async.wait_group 1;");
        else               asm volatile("cp.async.wait_group 0;");
        __syncthreads();

        const int bi = tile & 1;
        const float4* B4 = reinterpret_cast<const float4*>(buf + bi * TR * 256);
        const float* XZ = xyzs + bi * TR * 3;

        float keep = 0.0f;
#pragma unroll
        for (int rb = 0; rb < 2; rb++) {
            const int row = warp * 2 + rb;
            const float4 fa = B4[row * 64 + lane];
            const float4 fb = B4[row * 64 + 32 + lane];

            float p0, p1, p2, p3;
            p0 = fa.x * qa[0].x; p0 = fmaf(fa.y, qa[0].y, p0);
            p0 = fmaf(fa.z, qa[0].z, p0); p0 = fmaf(fa.w, qa[0].w, p0);
            p0 = fmaf(fb.x, qb[0].x, p0); p0 = fmaf(fb.y, qb[0].y, p0);
            p0 = fmaf(fb.z, qb[0].z, p0); p0 = fmaf(fb.w, qb[0].w, p0);

            p1 = fa.x * qa[1].x; p1 = fmaf(fa.y, qa[1].y, p1);
            p1 = fmaf(fa.z, qa[1].z, p1); p1 = fmaf(fa.w, qa[1].w, p1);
            p1 = fmaf(fb.x, qb[1].x, p1); p1 = fmaf(fb.y, qb[1].y, p1);
            p1 = fmaf(fb.z, qb[1].z, p1); p1 = fmaf(fb.w, qb[1].w, p1);

            p2 = fa.x * qa[2].x; p2 = fmaf(fa.y, qa[2].y, p2);
            p2 = fmaf(fa.z, qa[2].z, p2); p2 = fmaf(fa.w, qa[2].w, p2);
            p2 = fmaf(fb.x, qb[2].x, p2); p2 = fmaf(fb.y, qb[2].y, p2);
            p2 = fmaf(fb.z, qb[2].z, p2); p2 = fmaf(fb.w, qb[2].w, p2);

            p3 = fa.x * qa[3].x; p3 = fmaf(fa.y, qa[3].y, p3);
            p3 = fmaf(fa.z, qa[3].z, p3); p3 = fmaf(fa.w, qa[3].w, p3);
            p3 = fmaf(fb.x, qb[3].x, p3); p3 = fmaf(fb.y, qb[3].y, p3);
            p3 = fmaf(fb.w, qb[3].w, fmaf(fb.z, qb[3].z, p3));

            // Quad transpose-reduce: every lane ends with sum for k = lane&3
            float t1 = (lane & 1) ? p0 : p1;
            t1 = __shfl_xor_sync(0xffffffffu, t1, 1);
            float t2 = (lane & 1) ? p2 : p3;
            t2 = __shfl_xor_sync(0xffffffffu, t2, 1);
            const float aab = ((lane & 1) ? p1 : p0) + t1;
            const float ccd = ((lane & 1) ? p3 : p2) + t2;
            float t3 = (lane & 2) ? aab : ccd;
            t3 = __shfl_xor_sync(0xffffffffu, t3, 2);
            float v = ((lane & 2) ? ccd : aab) + t3;
            v += __shfl_xor_sync(0xffffffffu, v, 4);
            v += __shfl_xor_sync(0xffffffffu, v, 8);
            v += __shfl_xor_sync(0xffffffffu, v, 16);
            if (myrow == rb) keep = v;
        }

        const float wgt = __expf(keep * LOGIT_SCALE);
        if (lane < 8) {       // lane = 4*myrow + k
            const int row = warp * 2 + myrow;
            const float px = XZ[row * 3 + 0];
            const float py = XZ[row * 3 + 1];
            const float pz = XZ[row * 3 + 2];
            aw += wgt;
            ax = fmaf(wgt, px, ax);
            ay = fmaf(wgt, py, ay);
            az = fmaf(wgt, pz, az);
        }

        __syncthreads();

        if (tile + 2 < NT) {
            const float* src = fbase + (tile + 2) * TR * 256;
            float* dst = buf + bi * TR * 256;
#pragma unroll
            for (int j = 0; j < 4; j++) {
                const int f = (t + j * 256) * 4;
                cp16(dst + f, src + f);
            }
            if (t < TR * 3)
                cp4(xyzs + bi * TR * 3 + t, xbase + (tile + 2) * TR * 3 + t);
            cp_commit();
        }
    }

    // accumulators live in lanes 0..7 (seg,k); fold seg with one xor-4
    aw += __shfl_xor_sync(0xffffffffu, aw, 4);
    ax += __shfl_xor_sync(0xffffffffu, ax, 4);
    ay += __shfl_xor_sync(0xffffffffu, ay, 4);
    az += __shfl_xor_sync(0xffffffffu, az, 4);
    if (lane < 4)
        red4[warp * 4 + lane] = make_float4(aw, ax, ay, az);
    __syncthreads();

    if (t < 16) {
        const int k = t >> 2;
        const int c = t & 3;
        const float* rf = reinterpret_cast<const float*>(red4);
        float s = 0.0f;
#pragma unroll
        for (int j = 0; j < 8; j++) s += rf[(j * 4 + k) * 4 + c];
        atomicAdd(&g_acc[((size_t)b * K_DIM + k) * 4 + c], s);
    }
    __syncthreads();

    // last attn block finalizes coords and resets state for the next replay
    if (t == 0) {
        __threadfence();
        const int old = atomicAdd(&g_attn_done, 1);
        is_last = (old == ATTN_BLOCKS - 1);
    }
    __syncthreads();
    if (is_last) {
        if (t < B_DIM * K_DIM) {
            volatile float* ga = g_acc + (size_t)t * 4;
            const float sw = ga[0];
            const float sx = ga[1];
            const float sy = ga[2];
            const float sz = ga[3];
            const float inv = 1.0f / sw;
            out[OUT_COORDS + t * 3 + 0] = sx * inv;
            out[OUT_COORDS + t * 3 + 1] = sy * inv;
            out[OUT_COORDS + t * 3 + 2] = sz * inv;
            ga[0] = 0.0f; ga[1] = 0.0f; ga[2] = 0.0f; ga[3] = 0.0f;
        }
#pragma unroll
        for (int j = 0; j < 64; j++)
            g_q[t + j * 256] = 0.0f;
        __syncthreads();
        if (t == 0) {
            g_done = 0;
            g_attn_done = 0;
            __threadfence();
        }
    }
}

// ---------------------------------------------------------------------------
extern "C" void kernel_launch(void* const* d_in, const int* in_sizes, int n_in,
                              void* d_out, int out_size) {
    const float* hq    = (const float*)d_in[0];
    const float* oq    = (const float*)d_in[1];
    const float* feats = (const float*)d_in[2];
    const float* xyz   = (const float*)d_in[3];
    const float* W1    = (const float*)d_in[4];
    const float* b1    = (const float*)d_in[5];
    const float* W2    = (const float*)d_in[6];
    const float* b2    = (const float*)d_in[7];
    const float* Wq    = (const float*)d_in[8];
    const float* bq    = (const float*)d_in[9];
    float* out = (float*)d_out;

    cudaFuncSetAttribute(fused_kernel,
                         cudaFuncAttributeMaxDynamicSharedMemorySize,
                         SMEM_BYTES);

    fused_kernel<<<QP_BLOCKS + ATTN_BLOCKS + HH_BLOCKS, 256, SMEM_BYTES>>>(
        feats, xyz, hq, oq, W1, b1, W2, b2, Wq, bq, out);
}

// round 14
// speedup vs baseline: 1.1471x; 1.0652x over previous
#include <cuda_runtime.h>
#include <cuda_bf16.h>
#include <cstdint>

// Problem constants
#define B_DIM 16
#define P_DIM 87
#define K_DIM 4
#define N_DIM 32768
#define D_MODEL 256
#define HIDDEN 128
#define LOGIT_SCALE 0.125f   // ATTN_SCALE / TAU

// Output layout (flattened tuple, fp32)
#define OUT_PROBS 0
#define OUT_LOGITS 1392
#define OUT_COORDS 2784

// Scratch (no allocations allowed -> __device__ globals; zero-initialized,
// re-zeroed by the last attn block each launch for graph-replay safety)
__device__ float g_q[64 * D_MODEL];              // final projected queries
__device__ float g_acc[B_DIM * K_DIM * 4];       // per (b,k): sumw, sx, sy, sz
__device__ int   g_done = 0;                     // qproj completion counter
__device__ int   g_attn_done = 0;                // attn block completion counter

#define QP_BLOCKS 64        // 16 row-groups x 4 i-chunks
#define ATTN_BLOCKS 2048    // 128 x-tiles * 16 batches
#define HH_BLOCKS 348       // human-head blocks, 4 rows each
#define ATTN_BASE QP_BLOCKS                 // 64
#define HH_BASE (QP_BLOCKS + ATTN_BLOCKS)   // 2112

// Attn: each block covers 256 rows; warp w owns rows [w*32, w*32+32),
// processed 4 at a time through a warp-private double-buffered pipeline.
#define WROWS 4              // rows per warp-buffer
#define NTW 8                // iterations per warp (32 rows)
// smem: 8 warps * 2 * 4KB buffers (64KB) + 8*24 xyz floats + 32 float4 red
#define SMEM_BYTES 66816

// ---------------------------------------------------------------------------
// cp.async helpers
// ---------------------------------------------------------------------------
__device__ __forceinline__ void cp16(void* dst, const void* src) {
    uint32_t d = (uint32_t)__cvta_generic_to_shared(dst);
    asm volatile("cp.async.cg.shared.global [%0], [%1], 16;" :: "r"(d), "l"(src));
}
__device__ __forceinline__ void cp4(void* dst, const void* src) {
    uint32_t d = (uint32_t)__cvta_generic_to_shared(dst);
    asm volatile("cp.async.ca.shared.global [%0], [%1], 4;" :: "r"(d), "l"(src));
}
__device__ __forceinline__ void cp_commit() {
    asm volatile("cp.async.commit_group;");
}
__device__ __forceinline__ int ld_acquire(const int* p) {
    int v;
    asm volatile("ld.acquire.gpu.global.b32 %0, [%1];" : "=r"(v) : "l"(p));
    return v;
}

// ---------------------------------------------------------------------------
// Single fused kernel (R9 structure; attn mainloop is now warp-decoupled):
//   [0, 64):        q projection chunks -> atomicAdd g_q, release g_done
//   [64, 2112):     attention pooling (warp-private pipelines, no barriers)
//   [2112, 2460):   human MLP head
// ---------------------------------------------------------------------------
__global__ void __launch_bounds__(256, 3)
fused_kernel(const float* __restrict__ feats,
             const float* __restrict__ xyz,
             const float* __restrict__ hq,
             const float* __restrict__ oq,
             const float* __restrict__ W1,
             const float* __restrict__ b1,
             const float* __restrict__ W2,
             const float* __restrict__ b2,
             const float* __restrict__ Wq,
             const float* __restrict__ bq,
             float* __restrict__ out) {
    extern __shared__ float sm[];
    const int t = threadIdx.x;
    const int warp = t >> 5;
    const int lane = t & 31;

    if (blockIdx.x < QP_BLOCKS) {
        // ========== q projection chunk: 4 rows x 64-wide i-chunk ==========
        float* xs = sm;                                        // 256 floats
        float4* part4 = reinterpret_cast<float4*>(sm + 256);   // 32 KB
        const int rg = blockIdx.x >> 2;
        const int c = blockIdx.x & 3;

        {
            const int r = t >> 6;
            const int idx = t & 63;
            xs[r * 64 + idx] = oq[(size_t)(rg * 4 + r) * D_MODEL + c * 64 + idx];
        }
        __syncthreads();

        const float4* wqv = reinterpret_cast<const float4*>(Wq);
        float4 aA[4], aB[4];
#pragma unroll
        for (int r = 0; r < 4; r++) { aA[r] = {0,0,0,0}; aB[r] = {0,0,0,0}; }
#pragma unroll
        for (int ii = 0; ii < 8; ii++) {
            const int il = warp * 8 + ii;
            const int ig = c * 64 + il;
            const float4 wa = wqv[ig * 64 + lane];
            const float4 wb = wqv[ig * 64 + 32 + lane];
            const float x0 = xs[il];
            const float x1 = xs[64 + il];
            const float x2 = xs[128 + il];
            const float x3 = xs[192 + il];
            aA[0].x = fmaf(x0, wa.x, aA[0].x); aA[0].y = fmaf(x0, wa.y, aA[0].y);
            aA[0].z = fmaf(x0, wa.z, aA[0].z); aA[0].w = fmaf(x0, wa.w, aA[0].w);
            aB[0].x = fmaf(x0, wb.x, aB[0].x); aB[0].y = fmaf(x0, wb.y, aB[0].y);
            aB[0].z = fmaf(x0, wb.z, aB[0].z); aB[0].w = fmaf(x0, wb.w, aB[0].w);
            aA[1].x = fmaf(x1, wa.x, aA[1].x); aA[1].y = fmaf(x1, wa.y, aA[1].y);
            aA[1].z = fmaf(x1, wa.z, aA[1].z); aA[1].w = fmaf(x1, wa.w, aA[1].w);
            aB[1].x = fmaf(x1, wb.x, aB[1].x); aB[1].y = fmaf(x1, wb.y, aB[1].y);
            aB[1].z = fmaf(x1, wb.z, aB[1].z); aB[1].w = fmaf(x1, wb.w, aB[1].w);
            aA[2].x = fmaf(x2, wa.x, aA[2].x); aA[2].y = fmaf(x2, wa.y, aA[2].y);
            aA[2].z = fmaf(x2, wa.z, aA[2].z); aA[2].w = fmaf(x2, wa.w, aA[2].w);
            aB[2].x = fmaf(x2, wb.x, aB[2].x); aB[2].y = fmaf(x2, wb.y, aB[2].y);
            aB[2].z = fmaf(x2, wb.z, aB[2].z); aB[2].w = fmaf(x2, wb.w, aB[2].w);
            aA[3].x = fmaf(x3, wa.x, aA[3].x); aA[3].y = fmaf(x3, wa.y, aA[3].y);
            aA[3].z = fmaf(x3, wa.z, aA[3].z); aA[3].w = fmaf(x3, wa.w, aA[3].w);
            aB[3].x = fmaf(x3, wb.x, aB[3].x); aB[3].y = fmaf(x3, wb.y, aB[3].y);
            aB[3].z = fmaf(x3, wb.z, aB[3].z); aB[3].w = fmaf(x3, wb.w, aB[3].w);
        }
#pragma unroll
        for (int r = 0; r < 4; r++) {
            part4[(warp * 4 + r) * 64 + lane] = aA[r];
            part4[(warp * 4 + r) * 64 + 32 + lane] = aB[r];
        }
        __syncthreads();

        {
            const int r = t >> 6;
            const int cc = t & 63;
            float4 s = part4[r * 64 + cc];
#pragma unroll
            for (int j = 1; j < 8; j++) {
                const float4 p = part4[(j * 4 + r) * 64 + cc];
                s.x += p.x; s.y += p.y; s.z += p.z; s.w += p.w;
            }
            if (c == 0) {
                const float4 bb = reinterpret_cast<const float4*>(bq)[cc];
                s.x += bb.x; s.y += bb.y; s.z += bb.z; s.w += bb.w;
            }
            float* dst = g_q + (size_t)(rg * 4 + r) * D_MODEL + cc * 4;
            atomicAdd(dst + 0, s.x);
            atomicAdd(dst + 1, s.y);
            atomicAdd(dst + 2, s.z);
            atomicAdd(dst + 3, s.w);
        }
        __syncthreads();
        if (t == 0) {
            __threadfence();
            atomicAdd(&g_done, 1);
        }
        return;
    }

    if (blockIdx.x >= HH_BASE) {
        // ================= human head: 4 rows per block =================
        const int blk = blockIdx.x - HH_BASE;
        float* xs = sm;
        float4* part4 = reinterpret_cast<float4*>(sm + 1024);

        const float* src = hq + (size_t)blk * 4 * D_MODEL;
#pragma unroll
        for (int j = 0; j < 4; j++) xs[t + j * 256] = src[t + j * 256];
        __syncthreads();

        const int i0 = warp * 32;
        const float4* w1v = reinterpret_cast<const float4*>(W1);
        float4 a0 = {0,0,0,0}, a1 = {0,0,0,0}, a2 = {0,0,0,0}, a3 = {0,0,0,0};
#pragma unroll 4
        for (int ii = 0; ii < 32; ii++) {
            const int i = i0 + ii;
            const float4 wv = w1v[i * 32 + lane];
            const float x0 = xs[i];
            const float x1 = xs[256 + i];
            const float x2 = xs[512 + i];
            const float x3 = xs[768 + i];
            a0.x = fmaf(x0, wv.x, a0.x); a0.y = fmaf(x0, wv.y, a0.y);
            a0.z = fmaf(x0, wv.z, a0.z); a0.w = fmaf(x0, wv.w, a0.w);
            a1.x = fmaf(x1, wv.x, a1.x); a1.y = fmaf(x1, wv.y, a1.y);
            a1.z = fmaf(x1, wv.z, a1.z); a1.w = fmaf(x1, wv.w, a1.w);
            a2.x = fmaf(x2, wv.x, a2.x); a2.y = fmaf(x2, wv.y, a2.y);
            a2.z = fmaf(x2, wv.z, a2.z); a2.w = fmaf(x2, wv.w, a2.w);
            a3.x = fmaf(x3, wv.x, a3.x); a3.y = fmaf(x3, wv.y, a3.y);
            a3.z = fmaf(x3, wv.z, a3.z); a3.w = fmaf(x3, wv.w, a3.w);
        }
        part4[(warp * 4 + 0) * 32 + lane] = a0;
        part4[(warp * 4 + 1) * 32 + lane] = a1;
        part4[(warp * 4 + 2) * 32 + lane] = a2;
        part4[(warp * 4 + 3) * 32 + lane] = a3;
        __syncthreads();

        if (t < 128) {
            const int r = t >> 5;
            const int l = t & 31;
            float4 s = part4[r * 32 + l];
#pragma unroll
            for (int j = 1; j < 8; j++) {
                const float4 p = part4[(j * 4 + r) * 32 + l];
                s.x += p.x; s.y += p.y; s.z += p.z; s.w += p.w;
            }
            const float4 bb = reinterpret_cast<const float4*>(b1)[l];
            s.x = fmaxf(s.x + bb.x, 0.0f);
            s.y = fmaxf(s.y + bb.y, 0.0f);
            s.z = fmaxf(s.z + bb.z, 0.0f);
            s.w = fmaxf(s.w + bb.w, 0.0f);
            const float4 w2 = reinterpret_cast<const float4*>(W2)[l];
            float v = s.x * w2.x + s.y * w2.y + s.z * w2.z + s.w * w2.w;
#pragma unroll
            for (int off = 16; off > 0; off >>= 1)
                v += __shfl_xor_sync(0xffffffffu, v, off);
            if (l == 0) {
                const int row = blk * 4 + r;
                const float logit = v + b2[0];
                out[OUT_LOGITS + row] = logit;
                out[OUT_PROBS + row] = 1.0f / (1.0f + __expf(-logit));
            }
        }
        return;
    }

    // ================= attention pooling (warp-decoupled) =================
    const int abx = blockIdx.x - ATTN_BASE;   // 0..2047
    const int b = abx >> 7;                   // batch 0..15
    const int xt = abx & 127;                 // x-tile 0..127
    const int row0 = xt * 256 + warp * 32;    // this warp's first row

    // warp-private smem: 2 x 4-row (4KB) buffers + 2 x 12 xyz floats
    float* wbuf = sm + warp * 2048;                 // 8 KB per warp
    float* wxyz = sm + 16384 + warp * 24;
    float4* red4 = reinterpret_cast<float4*>(sm + 16384 + 192);
    __shared__ int is_last;

    const float* fbase = feats + ((size_t)b * N_DIM + row0) * D_MODEL;
    const float* xbase = xyz + ((size_t)b * N_DIM + row0) * 3;

    // prologue FIRST (independent of g_q): issue buffers 0 and 1
#pragma unroll
    for (int pt = 0; pt < 2; pt++) {
        const float* src = fbase + pt * WROWS * 256;
        float* dst = wbuf + pt * 1024;
#pragma unroll
        for (int j = 0; j < 8; j++) {
            const int f = (lane + j * 32) * 4;
            cp16(dst + f, src + f);
        }
        if (lane < WROWS * 3)
            cp4(wxyz + pt * 12 + lane, xbase + pt * WROWS * 3 + lane);
        cp_commit();
    }

    // acquire-spin until qproj is complete (overlaps first-buffer DRAM fetch)
    if (t == 0) {
        while (ld_acquire(&g_done) < QP_BLOCKS)
            __nanosleep(32);
    }
    __syncthreads();   // the only block barrier before the epilogue

    // q in registers
    const float4* q4 =
        reinterpret_cast<const float4*>(g_q + (size_t)b * K_DIM * D_MODEL);
    float4 qa[K_DIM], qb[K_DIM];
#pragma unroll
    for (int k = 0; k < K_DIM; k++) {
        qa[k] = q4[k * 64 + lane];
        qb[k] = q4[k * 64 + 32 + lane];
    }

    float aw = 0.0f, ax = 0.0f, ay = 0.0f, az = 0.0f;
    const int myrow = (lane >> 2) & 3;   // lanes<16: which row this lane owns

#pragma unroll 1
    for (int it = 0; it < NTW; it++) {
        if (it < NTW - 1) asm volatile("cp.async.wait_group 1;");
        else              asm volatile("cp.async.wait_group 0;");
        __syncwarp();

        const int bi = it & 1;
        const float4* B4 = reinterpret_cast<const float4*>(wbuf + bi * 1024);
        const float* XZ = wxyz + bi * 12;

        float keep = 0.0f;
#pragma unroll
        for (int rb = 0; rb < WROWS; rb++) {
            const float4 fa = B4[rb * 64 + lane];
            const float4 fb = B4[rb * 64 + 32 + lane];

            float p0, p1, p2, p3;
            p0 = fa.x * qa[0].x; p0 = fmaf(fa.y, qa[0].y, p0);
            p0 = fmaf(fa.z, qa[0].z, p0); p0 = fmaf(fa.w, qa[0].w, p0);
            p0 = fmaf(fb.x, qb[0].x, p0); p0 = fmaf(fb.y, qb[0].y, p0);
            p0 = fmaf(fb.z, qb[0].z, p0); p0 = fmaf(fb.w, qb[0].w, p0);

            p1 = fa.x * qa[1].x; p1 = fmaf(fa.y, qa[1].y, p1);
            p1 = fmaf(fa.z, qa[1].z, p1); p1 = fmaf(fa.w, qa[1].w, p1);
            p1 = fmaf(fb.x, qb[1].x, p1); p1 = fmaf(fb.y, qb[1].y, p1);
            p1 = fmaf(fb.z, qb[1].z, p1); p1 = fmaf(fb.w, qb[1].w, p1);

            p2 = fa.x * qa[2].x; p2 = fmaf(fa.y, qa[2].y, p2);
            p2 = fmaf(fa.z, qa[2].z, p2); p2 = fmaf(fa.w, qa[2].w, p2);
            p2 = fmaf(fb.x, qb[2].x, p2); p2 = fmaf(fb.y, qb[2].y, p2);
            p2 = fmaf(fb.z, qb[2].z, p2); p2 = fmaf(fb.w, qb[2].w, p2);

            p3 = fa.x * qa[3].x; p3 = fmaf(fa.y, qa[3].y, p3);
            p3 = fmaf(fa.z, qa[3].z, p3); p3 = fmaf(fa.w, qa[3].w, p3);
            p3 = fmaf(fb.x, qb[3].x, p3); p3 = fmaf(fb.y, qb[3].y, p3);
            p3 = fmaf(fb.w, qb[3].w, fmaf(fb.z, qb[3].z, p3));

            // Quad transpose-reduce: every lane ends with sum for k = lane&3
            float t1 = (lane & 1) ? p0 : p1;
            t1 = __shfl_xor_sync(0xffffffffu, t1, 1);
            float t2 = (lane & 1) ? p2 : p3;
            t2 = __shfl_xor_sync(0xffffffffu, t2, 1);
            const float aab = ((lane & 1) ? p1 : p0) + t1;
            const float ccd = ((lane & 1) ? p3 : p2) + t2;
            float t3 = (lane & 2) ? aab : ccd;
            t3 = __shfl_xor_sync(0xffffffffu, t3, 2);
            float v = ((lane & 2) ? ccd : aab) + t3;
            v += __shfl_xor_sync(0xffffffffu, v, 4);
            v += __shfl_xor_sync(0xffffffffu, v, 8);
            v += __shfl_xor_sync(0xffffffffu, v, 16);
            if (myrow == rb) keep = v;
        }

        const float wgt = __expf(keep * LOGIT_SCALE);
        if (lane < 16) {     // lane = 4*myrow + k
            const float px = XZ[myrow * 3 + 0];
            const float py = XZ[myrow * 3 + 1];
            const float pz = XZ[myrow * 3 + 2];
            aw += wgt;
            ax = fmaf(wgt, px, ax);
            ay = fmaf(wgt, py, ay);
            az = fmaf(wgt, pz, az);
        }

        __syncwarp();   // all lanes done reading wbuf[bi] before refill

        if (it + 2 < NTW) {
            const float* src = fbase + (it + 2) * WROWS * 256;
            float* dst = wbuf + bi * 1024;
#pragma unroll
            for (int j = 0; j < 8; j++) {
                const int f = (lane + j * 32) * 4;
                cp16(dst + f, src + f);
            }
            if (lane < WROWS * 3)
                cp4(wxyz + bi * 12 + lane, xbase + (it + 2) * WROWS * 3 + lane);
            cp_commit();
        }
    }

    // fold the 4 row-owners per k (lane bits 2-3), lanes<16 hold data
    aw += __shfl_xor_sync(0xffffffffu, aw, 4);
    ax += __shfl_xor_sync(0xffffffffu, ax, 4);
    ay += __shfl_xor_sync(0xffffffffu, ay, 4);
    az += __shfl_xor_sync(0xffffffffu, az, 4);
    aw += __shfl_xor_sync(0xffffffffu, aw, 8);
    ax += __shfl_xor_sync(0xffffffffu, ax, 8);
    ay += __shfl_xor_sync(0xffffffffu, ay, 8);
    az += __shfl_xor_sync(0xffffffffu, az, 8);
    if (lane < 4)
        red4[warp * 4 + lane] = make_float4(aw, ax, ay, az);
    __syncthreads();

    if (t < 16) {
        const int k = t >> 2;
        const int c = t & 3;
        const float* rf = reinterpret_cast<const float*>(red4);
        float s = 0.0f;
#pragma unroll
        for (int j = 0; j < 8; j++) s += rf[(j * 4 + k) * 4 + c];
        atomicAdd(&g_acc[((size_t)b * K_DIM + k) * 4 + c], s);
    }
    __syncthreads();

    // last attn block finalizes coords and resets state for the next replay
    if (t == 0) {
        __threadfence();
        const int old = atomicAdd(&g_attn_done, 1);
        is_last = (old == ATTN_BLOCKS - 1);
    }
    __syncthreads();
    if (is_last) {
        if (t < B_DIM * K_DIM) {
            volatile float* ga = g_acc + (size_t)t * 4;
            const float sw = ga[0];
            const float sx = ga[1];
            const float sy = ga[2];
            const float sz = ga[3];
            const float inv = 1.0f / sw;
            out[OUT_COORDS + t * 3 + 0] = sx * inv;
            out[OUT_COORDS + t * 3 + 1] = sy * inv;
            out[OUT_COORDS + t * 3 + 2] = sz * inv;
            ga[0] = 0.0f; ga[1] = 0.0f; ga[2] = 0.0f; ga[3] = 0.0f;
        }
#pragma unroll
        for (int j = 0; j < 64; j++)
            g_q[t + j * 256] = 0.0f;
        __syncthreads();
        if (t == 0) {
            g_done = 0;
            g_attn_done = 0;
            __threadfence();
        }
    }
}

// ---------------------------------------------------------------------------
extern "C" void kernel_launch(void* const* d_in, const int* in_sizes, int n_in,
                              void* d_out, int out_size) {
    const float* hq    = (const float*)d_in[0];
    const float* oq    = (const float*)d_in[1];
    const float* feats = (const float*)d_in[2];
    const float* xyz   = (const float*)d_in[3];
    const float* W1    = (const float*)d_in[4];
    const float* b1    = (const float*)d_in[5];
    const float* W2    = (const float*)d_in[6];
    const float* b2    = (const float*)d_in[7];
    const float* Wq    = (const float*)d_in[8];
    const float* bq    = (const float*)d_in[9];
    float* out = (float*)d_out;

    cudaFuncSetAttribute(fused_kernel,
                         cudaFuncAttributeMaxDynamicSharedMemorySize,
                         SMEM_BYTES);

    fused_kernel<<<QP_BLOCKS + ATTN_BLOCKS + HH_BLOCKS, 256, SMEM_BYTES>>>(
        feats, xyz, hq, oq, W1, b1, W2, b2, Wq, bq, out);
}

// round 15
// speedup vs baseline: 1.1787x; 1.0276x over previous
#include <cuda_runtime.h>
#include <cuda_bf16.h>
#include <cstdint>

// Problem constants
#define B_DIM 16
#define P_DIM 87
#define K_DIM 4
#define N_DIM 32768
#define D_MODEL 256
#define HIDDEN 128
#define LOGIT_SCALE 0.125f   // ATTN_SCALE / TAU

// Output layout (flattened tuple, fp32)
#define OUT_PROBS 0
#define OUT_LOGITS 1392
#define OUT_COORDS 2784

// Scratch (no allocations allowed -> __device__ globals; zero-initialized,
// re-zeroed by the last attn block each launch for graph-replay safety)
__device__ float g_q[64 * D_MODEL];              // final projected queries
__device__ float g_acc[B_DIM * K_DIM * 4];       // per (b,k): sumw, sx, sy, sz
__device__ int   g_done_rg[16];                  // per-row-group qproj counters
__device__ int   g_attn_done = 0;                // attn block completion counter

#define QP_BLOCKS 128       // 16 row-groups x 8 i-chunks (32 i's each)
#define ATTN_BLOCKS 2048    // 128 x-tiles * 16 batches
#define HH_BLOCKS 348       // human-head blocks, 4 rows each
#define ATTN_BASE QP_BLOCKS                 // 128
#define HH_BASE (QP_BLOCKS + ATTN_BLOCKS)   // 2176

// Attn: each block covers 256 rows; warp w owns rows [w*32, w*32+32),
// processed 4 at a time through a warp-private double-buffered pipeline.
#define WROWS 4              // rows per warp-buffer
#define NTW 8                // iterations per warp (32 rows)
// smem: 8 warps * 2 * 4KB buffers (64KB) + 8*24 xyz floats + 32 float4 red
#define SMEM_BYTES 66816

// ---------------------------------------------------------------------------
// cp.async helpers
// ---------------------------------------------------------------------------
__device__ __forceinline__ void cp16(void* dst, const void* src) {
    uint32_t d = (uint32_t)__cvta_generic_to_shared(dst);
    asm volatile("cp.async.cg.shared.global [%0], [%1], 16;" :: "r"(d), "l"(src));
}
__device__ __forceinline__ void cp4(void* dst, const void* src) {
    uint32_t d = (uint32_t)__cvta_generic_to_shared(dst);
    asm volatile("cp.async.ca.shared.global [%0], [%1], 4;" :: "r"(d), "l"(src));
}
__device__ __forceinline__ void cp_commit() {
    asm volatile("cp.async.commit_group;");
}
__device__ __forceinline__ int ld_acquire(const int* p) {
    int v;
    asm volatile("ld.acquire.gpu.global.b32 %0, [%1];" : "=r"(v) : "l"(p));
    return v;
}

// ---------------------------------------------------------------------------
// Single fused kernel:
//   [0, 128):       q projection chunks -> atomicAdd g_q, release g_done_rg
//   [128, 2176):    attention pooling (warp-private pipelines; per-batch spin)
//   [2176, 2524):   human MLP head
// ---------------------------------------------------------------------------
__global__ void __launch_bounds__(256, 3)
fused_kernel(const float* __restrict__ feats,
             const float* __restrict__ xyz,
             const float* __restrict__ hq,
             const float* __restrict__ oq,
             const float* __restrict__ W1,
             const float* __restrict__ b1,
             const float* __restrict__ W2,
             const float* __restrict__ b2,
             const float* __restrict__ Wq,
             const float* __restrict__ bq,
             float* __restrict__ out) {
    extern __shared__ float sm[];
    const int t = threadIdx.x;
    const int warp = t >> 5;
    const int lane = t & 31;

    if (blockIdx.x < QP_BLOCKS) {
        // ========== q projection chunk: 4 rows x 32-wide i-chunk ==========
        float* xs = sm;                                        // 128 floats
        float4* part4 = reinterpret_cast<float4*>(sm + 128);   // 32 KB
        const int rg = blockIdx.x >> 3;      // row group 0..15
        const int c = blockIdx.x & 7;        // i-chunk 0..7 (32 i's each)

        // stage the 4x32 slice of oq
        if (t < 128) {
            const int r = t >> 5;
            const int idx = t & 31;
            xs[r * 32 + idx] = oq[(size_t)(rg * 4 + r) * D_MODEL + c * 32 + idx];
        }
        __syncthreads();

        // warp owns 4 i's; lane owns output cols {4l..4l+3} and {128+4l..}
        const float4* wqv = reinterpret_cast<const float4*>(Wq);
        float4 aA[4], aB[4];
#pragma unroll
        for (int r = 0; r < 4; r++) { aA[r] = {0,0,0,0}; aB[r] = {0,0,0,0}; }
#pragma unroll
        for (int ii = 0; ii < 4; ii++) {
            const int il = warp * 4 + ii;          // 0..31 within chunk
            const int ig = c * 32 + il;            // global i
            const float4 wa = wqv[ig * 64 + lane];
            const float4 wb = wqv[ig * 64 + 32 + lane];
            const float x0 = xs[il];
            const float x1 = xs[32 + il];
            const float x2 = xs[64 + il];
            const float x3 = xs[96 + il];
            aA[0].x = fmaf(x0, wa.x, aA[0].x); aA[0].y = fmaf(x0, wa.y, aA[0].y);
            aA[0].z = fmaf(x0, wa.z, aA[0].z); aA[0].w = fmaf(x0, wa.w, aA[0].w);
            aB[0].x = fmaf(x0, wb.x, aB[0].x); aB[0].y = fmaf(x0, wb.y, aB[0].y);
            aB[0].z = fmaf(x0, wb.z, aB[0].z); aB[0].w = fmaf(x0, wb.w, aB[0].w);
            aA[1].x = fmaf(x1, wa.x, aA[1].x); aA[1].y = fmaf(x1, wa.y, aA[1].y);
            aA[1].z = fmaf(x1, wa.z, aA[1].z); aA[1].w = fmaf(x1, wa.w, aA[1].w);
            aB[1].x = fmaf(x1, wb.x, aB[1].x); aB[1].y = fmaf(x1, wb.y, aB[1].y);
            aB[1].z = fmaf(x1, wb.z, aB[1].z); aB[1].w = fmaf(x1, wb.w, aB[1].w);
            aA[2].x = fmaf(x2, wa.x, aA[2].x); aA[2].y = fmaf(x2, wa.y, aA[2].y);
            aA[2].z = fmaf(x2, wa.z, aA[2].z); aA[2].w = fmaf(x2, wa.w, aA[2].w);
            aB[2].x = fmaf(x2, wb.x, aB[2].x); aB[2].y = fmaf(x2, wb.y, aB[2].y);
            aB[2].z = fmaf(x2, wb.z, aB[2].z); aB[2].w = fmaf(x2, wb.w, aB[2].w);
            aA[3].x = fmaf(x3, wa.x, aA[3].x); aA[3].y = fmaf(x3, wa.y, aA[3].y);
            aA[3].z = fmaf(x3, wa.z, aA[3].z); aA[3].w = fmaf(x3, wa.w, aA[3].w);
            aB[3].x = fmaf(x3, wb.x, aB[3].x); aB[3].y = fmaf(x3, wb.y, aB[3].y);
            aB[3].z = fmaf(x3, wb.z, aB[3].z); aB[3].w = fmaf(x3, wb.w, aB[3].w);
        }
#pragma unroll
        for (int r = 0; r < 4; r++) {
            part4[(warp * 4 + r) * 64 + lane] = aA[r];
            part4[(warp * 4 + r) * 64 + 32 + lane] = aB[r];
        }
        __syncthreads();

        {
            const int r = t >> 6;
            const int cc = t & 63;
            float4 s = part4[r * 64 + cc];
#pragma unroll
            for (int j = 1; j < 8; j++) {
                const float4 p = part4[(j * 4 + r) * 64 + cc];
                s.x += p.x; s.y += p.y; s.z += p.z; s.w += p.w;
            }
            if (c == 0) {
                const float4 bb = reinterpret_cast<const float4*>(bq)[cc];
                s.x += bb.x; s.y += bb.y; s.z += bb.z; s.w += bb.w;
            }
            float* dst = g_q + (size_t)(rg * 4 + r) * D_MODEL + cc * 4;
            atomicAdd(dst + 0, s.x);
            atomicAdd(dst + 1, s.y);
            atomicAdd(dst + 2, s.z);
            atomicAdd(dst + 3, s.w);
        }
        __syncthreads();
        if (t == 0) {
            __threadfence();
            atomicAdd(&g_done_rg[rg], 1);
        }
        return;
    }

    if (blockIdx.x >= HH_BASE) {
        // ================= human head: 4 rows per block =================
        const int blk = blockIdx.x - HH_BASE;
        float* xs = sm;
        float4* part4 = reinterpret_cast<float4*>(sm + 1024);

        const float* src = hq + (size_t)blk * 4 * D_MODEL;
#pragma unroll
        for (int j = 0; j < 4; j++) xs[t + j * 256] = src[t + j * 256];
        __syncthreads();

        const int i0 = warp * 32;
        const float4* w1v = reinterpret_cast<const float4*>(W1);
        float4 a0 = {0,0,0,0}, a1 = {0,0,0,0}, a2 = {0,0,0,0}, a3 = {0,0,0,0};
#pragma unroll 4
        for (int ii = 0; ii < 32; ii++) {
            const int i = i0 + ii;
            const float4 wv = w1v[i * 32 + lane];
            const float x0 = xs[i];
            const float x1 = xs[256 + i];
            const float x2 = xs[512 + i];
            const float x3 = xs[768 + i];
            a0.x = fmaf(x0, wv.x, a0.x); a0.y = fmaf(x0, wv.y, a0.y);
            a0.z = fmaf(x0, wv.z, a0.z); a0.w = fmaf(x0, wv.w, a0.w);
            a1.x = fmaf(x1, wv.x, a1.x); a1.y = fmaf(x1, wv.y, a1.y);
            a1.z = fmaf(x1, wv.z, a1.z); a1.w = fmaf(x1, wv.w, a1.w);
            a2.x = fmaf(x2, wv.x, a2.x); a2.y = fmaf(x2, wv.y, a2.y);
            a2.z = fmaf(x2, wv.z, a2.z); a2.w = fmaf(x2, wv.w, a2.w);
            a3.x = fmaf(x3, wv.x, a3.x); a3.y = fmaf(x3, wv.y, a3.y);
            a3.z = fmaf(x3, wv.z, a3.z); a3.w = fmaf(x3, wv.w, a3.w);
        }
        part4[(warp * 4 + 0) * 32 + lane] = a0;
        part4[(warp * 4 + 1) * 32 + lane] = a1;
        part4[(warp * 4 + 2) * 32 + lane] = a2;
        part4[(warp * 4 + 3) * 32 + lane] = a3;
        __syncthreads();

        if (t < 128) {
            const int r = t >> 5;
            const int l = t & 31;
            float4 s = part4[r * 32 + l];
#pragma unroll
            for (int j = 1; j < 8; j++) {
                const float4 p = part4[(j * 4 + r) * 32 + l];
                s.x += p.x; s.y += p.y; s.z += p.z; s.w += p.w;
            }
            const float4 bb = reinterpret_cast<const float4*>(b1)[l];
            s.x = fmaxf(s.x + bb.x, 0.0f);
            s.y = fmaxf(s.y + bb.y, 0.0f);
            s.z = fmaxf(s.z + bb.z, 0.0f);
            s.w = fmaxf(s.w + bb.w, 0.0f);
            const float4 w2 = reinterpret_cast<const float4*>(W2)[l];
            float v = s.x * w2.x + s.y * w2.y + s.z * w2.z + s.w * w2.w;
#pragma unroll
            for (int off = 16; off > 0; off >>= 1)
                v += __shfl_xor_sync(0xffffffffu, v, off);
            if (l == 0) {
                const int row = blk * 4 + r;
                const float logit = v + b2[0];
                out[OUT_LOGITS + row] = logit;
                out[OUT_PROBS + row] = 1.0f / (1.0f + __expf(-logit));
            }
        }
        return;
    }

    // ================= attention pooling (warp-decoupled) =================
    const int abx = blockIdx.x - ATTN_BASE;   // 0..2047
    const int b = abx >> 7;                   // batch 0..15
    const int xt = abx & 127;                 // x-tile 0..127
    const int row0 = xt * 256 + warp * 32;    // this warp's first row

    // warp-private smem: 2 x 4-row (4KB) buffers + 2 x 12 xyz floats
    float* wbuf = sm + warp * 2048;                 // 8 KB per warp
    float* wxyz = sm + 16384 + warp * 24;
    float4* red4 = reinterpret_cast<float4*>(sm + 16384 + 192);
    __shared__ int is_last;

    const float* fbase = feats + ((size_t)b * N_DIM + row0) * D_MODEL;
    const float* xbase = xyz + ((size_t)b * N_DIM + row0) * 3;

    // prologue FIRST (independent of g_q): issue buffers 0 and 1
#pragma unroll
    for (int pt = 0; pt < 2; pt++) {
        const float* src = fbase + pt * WROWS * 256;
        float* dst = wbuf + pt * 1024;
#pragma unroll
        for (int j = 0; j < 8; j++) {
            const int f = (lane + j * 32) * 4;
            cp16(dst + f, src + f);
        }
        if (lane < WROWS * 3)
            cp4(wxyz + pt * 12 + lane, xbase + pt * WROWS * 3 + lane);
        cp_commit();
    }

    // acquire-spin until THIS batch's 8 qproj chunk blocks are done
    if (t == 0) {
        while (ld_acquire(&g_done_rg[b]) < 8)
            __nanosleep(32);
    }
    __syncthreads();   // the only block barrier before the epilogue

    // q in registers
    const float4* q4 =
        reinterpret_cast<const float4*>(g_q + (size_t)b * K_DIM * D_MODEL);
    float4 qa[K_DIM], qb[K_DIM];
#pragma unroll
    for (int k = 0; k < K_DIM; k++) {
        qa[k] = q4[k * 64 + lane];
        qb[k] = q4[k * 64 + 32 + lane];
    }

    float aw = 0.0f, ax = 0.0f, ay = 0.0f, az = 0.0f;
    const int myrow = (lane >> 2) & 3;   // lanes<16: which row this lane owns

#pragma unroll 1
    for (int it = 0; it < NTW; it++) {
        if (it < NTW - 1) asm volatile("cp.async.wait_group 1;");
        else              asm volatile("cp.async.wait_group 0;");
        __syncwarp();

        const int bi = it & 1;
        const float4* B4 = reinterpret_cast<const float4*>(wbuf + bi * 1024);
        const float* XZ = wxyz + bi * 12;

        float keep = 0.0f;
#pragma unroll
        for (int rb = 0; rb < WROWS; rb++) {
            const float4 fa = B4[rb * 64 + lane];
            const float4 fb = B4[rb * 64 + 32 + lane];

            float p0, p1, p2, p3;
            p0 = fa.x * qa[0].x; p0 = fmaf(fa.y, qa[0].y, p0);
            p0 = fmaf(fa.z, qa[0].z, p0); p0 = fmaf(fa.w, qa[0].w, p0);
            p0 = fmaf(fb.x, qb[0].x, p0); p0 = fmaf(fb.y, qb[0].y, p0);
            p0 = fmaf(fb.z, qb[0].z, p0); p0 = fmaf(fb.w, qb[0].w, p0);

            p1 = fa.x * qa[1].x; p1 = fmaf(fa.y, qa[1].y, p1);
            p1 = fmaf(fa.z, qa[1].z, p1); p1 = fmaf(fa.w, qa[1].w, p1);
            p1 = fmaf(fb.x, qb[1].x, p1); p1 = fmaf(fb.y, qb[1].y, p1);
            p1 = fmaf(fb.z, qb[1].z, p1); p1 = fmaf(fb.w, qb[1].w, p1);

            p2 = fa.x * qa[2].x; p2 = fmaf(fa.y, qa[2].y, p2);
            p2 = fmaf(fa.z, qa[2].z, p2); p2 = fmaf(fa.w, qa[2].w, p2);
            p2 = fmaf(fb.x, qb[2].x, p2); p2 = fmaf(fb.y, qb[2].y, p2);
            p2 = fmaf(fb.z, qb[2].z, p2); p2 = fmaf(fb.w, qb[2].w, p2);

            p3 = fa.x * qa[3].x; p3 = fmaf(fa.y, qa[3].y, p3);
            p3 = fmaf(fa.z, qa[3].z, p3); p3 = fmaf(fa.w, qa[3].w, p3);
            p3 = fmaf(fb.x, qb[3].x, p3); p3 = fmaf(fb.y, qb[3].y, p3);
            p3 = fmaf(fb.w, qb[3].w, fmaf(fb.z, qb[3].z, p3));

            // Quad transpose-reduce: every lane ends with sum for k = lane&3
            float t1 = (lane & 1) ? p0 : p1;
            t1 = __shfl_xor_sync(0xffffffffu, t1, 1);
            float t2 = (lane & 1) ? p2 : p3;
            t2 = __shfl_xor_sync(0xffffffffu, t2, 1);
            const float aab = ((lane & 1) ? p1 : p0) + t1;
            const float ccd = ((lane & 1) ? p3 : p2) + t2;
            float t3 = (lane & 2) ? aab : ccd;
            t3 = __shfl_xor_sync(0xffffffffu, t3, 2);
            float v = ((lane & 2) ? ccd : aab) + t3;
            v += __shfl_xor_sync(0xffffffffu, v, 4);
            v += __shfl_xor_sync(0xffffffffu, v, 8);
            v += __shfl_xor_sync(0xffffffffu, v, 16);
            if (myrow == rb) keep = v;
        }

        const float wgt = __expf(keep * LOGIT_SCALE);
        if (lane < 16) {     // lane = 4*myrow + k
            const float px = XZ[myrow * 3 + 0];
            const float py = XZ[myrow * 3 + 1];
            const float pz = XZ[myrow * 3 + 2];
            aw += wgt;
            ax = fmaf(wgt, px, ax);
            ay = fmaf(wgt, py, ay);
            az = fmaf(wgt, pz, az);
        }

        __syncwarp();   // all lanes done reading wbuf[bi] before refill

        if (it + 2 < NTW) {
            const float* src = fbase + (it + 2) * WROWS * 256;
            float* dst = wbuf + bi * 1024;
#pragma unroll
            for (int j = 0; j < 8; j++) {
                const int f = (lane + j * 32) * 4;
                cp16(dst + f, src + f);
            }
            if (lane < WROWS * 3)
                cp4(wxyz + bi * 12 + lane, xbase + (it + 2) * WROWS * 3 + lane);
            cp_commit();
        }
    }

    // fold the 4 row-owners per k (lane bits 2-3), lanes<16 hold data
    aw += __shfl_xor_sync(0xffffffffu, aw, 4);
    ax += __shfl_xor_sync(0xffffffffu, ax, 4);
    ay += __shfl_xor_sync(0xffffffffu, ay, 4);
    az += __shfl_xor_sync(0xffffffffu, az, 4);
    aw += __shfl_xor_sync(0xffffffffu, aw, 8);
    ax += __shfl_xor_sync(0xffffffffu, ax, 8);
    ay += __shfl_xor_sync(0xffffffffu, ay, 8);
    az += __shfl_xor_sync(0xffffffffu, az, 8);
    if (lane < 4)
        red4[warp * 4 + lane] = make_float4(aw, ax, ay, az);
    __syncthreads();

    if (t < 16) {
        const int k = t >> 2;
        const int c = t & 3;
        const float* rf = reinterpret_cast<const float*>(red4);
        float s = 0.0f;
#pragma unroll
        for (int j = 0; j < 8; j++) s += rf[(j * 4 + k) * 4 + c];
        atomicAdd(&g_acc[((size_t)b * K_DIM + k) * 4 + c], s);
    }
    __syncthreads();

    // last attn block finalizes coords and resets state for the next replay
    if (t == 0) {
        __threadfence();
        const int old = atomicAdd(&g_attn_done, 1);
        is_last = (old == ATTN_BLOCKS - 1);
    }
    __syncthreads();
    if (is_last) {
        if (t < B_DIM * K_DIM) {
            volatile float* ga = g_acc + (size_t)t * 4;
            const float sw = ga[0];
            const float sx = ga[1];
            const float sy = ga[2];
            const float sz = ga[3];
            const float inv = 1.0f / sw;
            out[OUT_COORDS + t * 3 + 0] = sx * inv;
            out[OUT_COORDS + t * 3 + 1] = sy * inv;
            out[OUT_COORDS + t * 3 + 2] = sz * inv;
            ga[0] = 0.0f; ga[1] = 0.0f; ga[2] = 0.0f; ga[3] = 0.0f;
        }
        if (t < 16) g_done_rg[t] = 0;
#pragma unroll
        for (int j = 0; j < 64; j++)
            g_q[t + j * 256] = 0.0f;
        __syncthreads();
        if (t == 0) {
            g_attn_done = 0;
            __threadfence();
        }
    }
}

// ---------------------------------------------------------------------------
extern "C" void kernel_launch(void* const* d_in, const int* in_sizes, int n_in,
                              void* d_out, int out_size) {
    const float* hq    = (const float*)d_in[0];
    const float* oq    = (const float*)d_in[1];
    const float* feats = (const float*)d_in[2];
    const float* xyz   = (const float*)d_in[3];
    const float* W1    = (const float*)d_in[4];
    const float* b1    = (const float*)d_in[5];
    const float* W2    = (const float*)d_in[6];
    const float* b2    = (const float*)d_in[7];
    const float* Wq    = (const float*)d_in[8];
    const float* bq    = (const float*)d_in[9];
    float* out = (float*)d_out;

    cudaFuncSetAttribute(fused_kernel,
                         cudaFuncAttributeMaxDynamicSharedMemorySize,
                         SMEM_BYTES);

    fused_kernel<<<QP_BLOCKS + ATTN_BLOCKS + HH_BLOCKS, 256, SMEM_BYTES>>>(
        feats, xyz, hq, oq, W1, b1, W2, b2, Wq, bq, out);
}